// round 4
// baseline (speedup 1.0000x reference)
#include <cuda_runtime.h>

// out[i, :] = values[i] * W_D[layer_idx[i], feat_idx[i], :]
// W_D: (12, 16384, 768) fp32; nnz = 131072; d_model = 768 (3072 B/row).
// 8 rows per CTA, 192 threads; each thread issues 8 independent float4
// gathers (MLP=8) before any consume, then 8 streaming stores (__stcs
// keeps L2 capacity for W-row duplicate reuse).

#define D_SAE   16384
#define D_MODEL 768
#define VEC_PER_ROW (D_MODEL / 4)   // 192
#define ROWS_PER_CTA 8

__global__ __launch_bounds__(VEC_PER_ROW)
void gather_scale_kernel(const float4* __restrict__ W,
                         const float*  __restrict__ vals,
                         const int*    __restrict__ li,
                         const int*    __restrict__ fi,
                         float4*       __restrict__ out)
{
    const int row0 = blockIdx.x * ROWS_PER_CTA;
    const int c    = threadIdx.x;

    unsigned int src[ROWS_PER_CTA];
    float        v[ROWS_PER_CTA];

#pragma unroll
    for (int r = 0; r < ROWS_PER_CTA; r++) {
        const int row   = row0 + r;
        const int layer = __ldg(&li[row]);
        const int feat  = __ldg(&fi[row]);
        v[r]            = __ldg(&vals[row]);
        src[r] = (unsigned int)(layer * D_SAE + feat) * VEC_PER_ROW + c;
    }

    // 8 independent gathers in flight per thread
    float4 d[ROWS_PER_CTA];
#pragma unroll
    for (int r = 0; r < ROWS_PER_CTA; r++)
        d[r] = __ldg(&W[src[r]]);

#pragma unroll
    for (int r = 0; r < ROWS_PER_CTA; r++) {
        float4 o = d[r];
        o.x *= v[r]; o.y *= v[r]; o.z *= v[r]; o.w *= v[r];
        __stcs(&out[(unsigned int)(row0 + r) * VEC_PER_ROW + c], o);
    }
}

extern "C" void kernel_launch(void* const* d_in, const int* in_sizes, int n_in,
                              void* d_out, int out_size)
{
    const float4* W    = (const float4*)d_in[0];
    const float*  vals = (const float*) d_in[1];
    const int*    li   = (const int*)   d_in[2];
    // d_in[3] = pos_idx (unused)
    const int*    fi   = (const int*)   d_in[4];
    float4*       out  = (float4*)      d_out;

    const int nnz  = in_sizes[1];                // 131072 (divisible by 8)
    const int grid = nnz / ROWS_PER_CTA;         // 16384

    gather_scale_kernel<<<grid, VEC_PER_ROW>>>(W, vals, li, fi, out);
}

// round 6
// speedup vs baseline: 1.0047x; 1.0047x over previous
#include <cuda_runtime.h>

// out[i, :] = values[i] * W_D[layer_idx[i], feat_idx[i], :]
// W_D: (12, 16384, 768) fp32; nnz = 131072; d_model = 768 (3072 B/row).
// 8 rows per CTA, 192 threads. __launch_bounds__(192, 6) grants ~56 regs/thread
// so ptxas keeps all 8 float4 gathers in flight (true MLP=8).
// Gathers use __ldcg (L2-only; L1 has ~0 hit rate on random rows).
// Stores use __stcs (evict-first; keep L2 for duplicated W rows).

#define D_SAE   16384
#define D_MODEL 768
#define VEC_PER_ROW (D_MODEL / 4)   // 192
#define ROWS_PER_CTA 8

__global__ __launch_bounds__(VEC_PER_ROW, 6)
void gather_scale_kernel(const float4* __restrict__ W,
                         const float*  __restrict__ vals,
                         const int*    __restrict__ li,
                         const int*    __restrict__ fi,
                         float4*       __restrict__ out)
{
    const int row0 = blockIdx.x * ROWS_PER_CTA;
    const int c    = threadIdx.x;

    unsigned int src[ROWS_PER_CTA];
    float        v[ROWS_PER_CTA];

#pragma unroll
    for (int r = 0; r < ROWS_PER_CTA; r++) {
        const int row   = row0 + r;
        const int layer = __ldg(&li[row]);
        const int feat  = __ldg(&fi[row]);
        v[r]            = __ldg(&vals[row]);
        src[r] = (unsigned int)(layer * D_SAE + feat) * VEC_PER_ROW + c;
    }

    // 8 independent L2-only gathers in flight per thread
    float4 d[ROWS_PER_CTA];
#pragma unroll
    for (int r = 0; r < ROWS_PER_CTA; r++)
        d[r] = __ldcg(&W[src[r]]);

#pragma unroll
    for (int r = 0; r < ROWS_PER_CTA; r++) {
        float4 o = d[r];
        o.x *= v[r]; o.y *= v[r]; o.z *= v[r]; o.w *= v[r];
        __stcs(&out[(unsigned int)(row0 + r) * VEC_PER_ROW + c], o);
    }
}

extern "C" void kernel_launch(void* const* d_in, const int* in_sizes, int n_in,
                              void* d_out, int out_size)
{
    const float4* W    = (const float4*)d_in[0];
    const float*  vals = (const float*) d_in[1];
    const int*    li   = (const int*)   d_in[2];
    // d_in[3] = pos_idx (unused)
    const int*    fi   = (const int*)   d_in[4];
    float4*       out  = (float4*)      d_out;

    const int nnz  = in_sizes[1];                // 131072 (divisible by 8)
    const int grid = nnz / ROWS_PER_CTA;         // 16384

    gather_scale_kernel<<<grid, VEC_PER_ROW>>>(W, vals, li, fi, out);
}

// round 7
// speedup vs baseline: 1.0068x; 1.0021x over previous
#include <cuda_runtime.h>

// out[i, :] = values[i] * W_D[layer_idx[i], feat_idx[i], :]
// W_D: (12, 16384, 768) fp32; nnz = 131072; d_model = 768 (3072 B/row).
// 8 rows per CTA, 192 threads, true MLP=8 (launch_bounds grants regs).
// Gathers: __ldcg (L2-only). Stores: __stwt (write-through, no L2
// allocation) so the per-layer W working set (~24.5 MB distinct rows)
// stays L2-resident and duplicate-feature gathers hit L2 instead of DRAM.

#define D_SAE   16384
#define D_MODEL 768
#define VEC_PER_ROW (D_MODEL / 4)   // 192
#define ROWS_PER_CTA 8

__global__ __launch_bounds__(VEC_PER_ROW, 6)
void gather_scale_kernel(const float4* __restrict__ W,
                         const float*  __restrict__ vals,
                         const int*    __restrict__ li,
                         const int*    __restrict__ fi,
                         float4*       __restrict__ out)
{
    const int row0 = blockIdx.x * ROWS_PER_CTA;
    const int c    = threadIdx.x;

    unsigned int src[ROWS_PER_CTA];
    float        v[ROWS_PER_CTA];

#pragma unroll
    for (int r = 0; r < ROWS_PER_CTA; r++) {
        const int row   = row0 + r;
        const int layer = __ldg(&li[row]);
        const int feat  = __ldg(&fi[row]);
        v[r]            = __ldg(&vals[row]);
        src[r] = (unsigned int)(layer * D_SAE + feat) * VEC_PER_ROW + c;
    }

    // 8 independent L2-only gathers in flight per thread
    float4 d[ROWS_PER_CTA];
#pragma unroll
    for (int r = 0; r < ROWS_PER_CTA; r++)
        d[r] = __ldcg(&W[src[r]]);

#pragma unroll
    for (int r = 0; r < ROWS_PER_CTA; r++) {
        float4 o = d[r];
        o.x *= v[r]; o.y *= v[r]; o.z *= v[r]; o.w *= v[r];
        // write-through: full-sector store, no L2 allocation -> L2 stays
        // free for the gathered W rows (duplicate reuse)
        __stwt(&out[(unsigned int)(row0 + r) * VEC_PER_ROW + c], o);
    }
}

extern "C" void kernel_launch(void* const* d_in, const int* in_sizes, int n_in,
                              void* d_out, int out_size)
{
    const float4* W    = (const float4*)d_in[0];
    const float*  vals = (const float*) d_in[1];
    const int*    li   = (const int*)   d_in[2];
    // d_in[3] = pos_idx (unused)
    const int*    fi   = (const int*)   d_in[4];
    float4*       out  = (float4*)      d_out;

    const int nnz  = in_sizes[1];                // 131072 (divisible by 8)
    const int grid = nnz / ROWS_PER_CTA;         // 16384

    gather_scale_kernel<<<grid, VEC_PER_ROW>>>(W, vals, li, fi, out);
}